// round 3
// baseline (speedup 1.0000x reference)
#include <cuda_runtime.h>

#define DEV_INLINE __device__ __forceinline__

static constexpr int V  = 32000;
static constexpr int H  = 512;
static constexpr int Bz = 64;
static constexpr int S  = 128;
static constexpr int H2 = 1024;   // 2H
static constexpr int G4 = 2048;   // 4H
static constexpr int G8 = 4096;   // 8H
static constexpr int R  = S * Bz; // 8192 rows of the (S,B) layout

// ---------------- scratch (device globals; no allocation allowed) ----------
__device__ float g_X  [R * H];    // gathered embeddings, (S*B, H)
__device__ float g_GF [R * G4];   // X@wih_f^T + bih_f + bhh_f
__device__ float g_GB [R * G4];   // X@wih_b^T + bih_b + bhh_b
__device__ float g_XIN[R * H2];   // [fwd | bwd] per scan index t
__device__ float g_G1 [R * G8];   // XIN@wih1^T + bih1 + bhh1
__device__ float g_Cf [Bz * H];
__device__ float g_Cb [Bz * H];
__device__ float g_H1a[Bz * H2];
__device__ float g_H1b[Bz * H2];
__device__ float g_H2a[Bz * H2];
__device__ float g_H2b[Bz * H2];
__device__ float g_C2 [Bz * H2];

// ---------------- packed f32x2 helpers -------------------------------------
DEV_INLINE unsigned long long pk2(float x, float y) {
    unsigned long long r;
    asm("mov.b64 %0, {%1, %2};" : "=l"(r) : "f"(x), "f"(y));
    return r;
}
DEV_INLINE float2 upk2(unsigned long long v) {
    float2 r;
    asm("mov.b64 {%0, %1}, %2;" : "=f"(r.x), "=f"(r.y) : "l"(v));
    return r;
}
#define FMA2(d, a, b) asm("fma.rn.f32x2 %0, %1, %2, %0;" : "+l"(d) : "l"(a), "l"(b))

DEV_INLINE float sigf(float x) { return 1.f / (1.f + expf(-x)); }

// ---------------- embedding gather ------------------------------------------
// row r of (S,B,H) = E[x_flat[r]]; token 0 -> zero row (padding_idx)
__global__ void k_embed(const int* __restrict__ x, const float* __restrict__ emb) {
    int r = blockIdx.x;
    int tok = x[r];
    float4 v = make_float4(0.f, 0.f, 0.f, 0.f);
    if (tok != 0)
        v = *(const float4*)(emb + (size_t)tok * H + threadIdx.x * 4);
    *(float4*)(g_X + (size_t)r * H + threadIdx.x * 4) = v;
}

// ---------------- initial-state copy ----------------------------------------
__global__ void k_init(const float* __restrict__ h01, const float* __restrict__ h02,
                       const float* __restrict__ c02, const float* __restrict__ c0f,
                       const float* __restrict__ c0b) {
    int i = blockIdx.x * blockDim.x + threadIdx.x; // 1024*256 = 262144 exactly
    if      (i < 65536)  g_H1a[i]          = h01[i];
    else if (i < 131072) g_H2a[i - 65536]  = h02[i - 65536];
    else if (i < 196608) g_C2 [i - 131072] = c02[i - 131072];
    else if (i < 229376) g_Cf [i - 196608] = c0f[i - 196608];
    else                 g_Cb [i - 229376] = c0b[i - 229376];
}

// ---------------- big batched GEMM: C[M,N] = A[M,K] @ W[N,K]^T + b1 + b2 ----
// 256 threads; BM x 64 tile; per-thread RPT x 4 outputs; f32x2 inner loop.
template <int BM>
__global__ void k_gemm_bias(const float* __restrict__ A,
                            const float* __restrict__ Wt,
                            const float* __restrict__ b1,
                            const float* __restrict__ b2,
                            float* __restrict__ C,
                            int K, int N) {
    constexpr int BN = 64, BK = 16, RPT = BM / 16;
    __shared__ float As[BK][BM + 4];
    __shared__ float Bs[BK][BN + 4];
    const int tid = threadIdx.x;
    const int bm = blockIdx.y * BM, bn = blockIdx.x * BN;
    const int tx = tid & 15, ty = tid >> 4;

    unsigned long long acc[RPT][2];
#pragma unroll
    for (int r = 0; r < RPT; r++) { acc[r][0] = 0ull; acc[r][1] = 0ull; }

    for (int k0 = 0; k0 < K; k0 += BK) {
#pragma unroll
        for (int i = tid; i < BM * 4; i += 256) {
            int m = i >> 2, kq = i & 3;
            float4 v = *(const float4*)(A + (size_t)(bm + m) * K + k0 + kq * 4);
            As[kq * 4 + 0][m] = v.x; As[kq * 4 + 1][m] = v.y;
            As[kq * 4 + 2][m] = v.z; As[kq * 4 + 3][m] = v.w;
        }
        {
            int n = tid >> 2, kq = tid & 3;
            float4 v = *(const float4*)(Wt + (size_t)(bn + n) * K + k0 + kq * 4);
            Bs[kq * 4 + 0][n] = v.x; Bs[kq * 4 + 1][n] = v.y;
            Bs[kq * 4 + 2][n] = v.z; Bs[kq * 4 + 3][n] = v.w;
        }
        __syncthreads();
#pragma unroll
        for (int kk = 0; kk < BK; kk++) {
            float2 bv0 = *(const float2*)&Bs[kk][tx * 4];
            float2 bv1 = *(const float2*)&Bs[kk][tx * 4 + 2];
            unsigned long long bp0 = pk2(bv0.x, bv0.y);
            unsigned long long bp1 = pk2(bv1.x, bv1.y);
#pragma unroll
            for (int r = 0; r < RPT; r++) {
                float a = As[kk][ty * RPT + r];
                unsigned long long ap = pk2(a, a);
                FMA2(acc[r][0], ap, bp0);
                FMA2(acc[r][1], ap, bp1);
            }
        }
        __syncthreads();
    }

    const int ncol = bn + tx * 4;
    float bb0 = b1[ncol + 0] + (b2 ? b2[ncol + 0] : 0.f);
    float bb1 = b1[ncol + 1] + (b2 ? b2[ncol + 1] : 0.f);
    float bb2 = b1[ncol + 2] + (b2 ? b2[ncol + 2] : 0.f);
    float bb3 = b1[ncol + 3] + (b2 ? b2[ncol + 3] : 0.f);
#pragma unroll
    for (int r = 0; r < RPT; r++) {
        float2 v0 = upk2(acc[r][0]);
        float2 v1 = upk2(acc[r][1]);
        float4 o = make_float4(v0.x + bb0, v0.y + bb1, v1.x + bb2, v1.y + bb3);
        *(float4*)(C + (size_t)(bm + ty * RPT + r) * N + ncol) = o;
    }
}

// ---------------- fused step GEMM core --------------------------------------
// Block covers 64 batch rows x (8 j-cols x 4 gates). acc[r][0]=(i,f), acc[r][1]=(g,o)
// for rows r0, r0+1.  HHg = gate stride in W's row index (H or H2).
template <int HHg>
DEV_INLINE void step_gemm(const float* __restrict__ hprev, int hstride,
                          const float* __restrict__ Whh, int K,
                          int j0, int tid,
                          unsigned long long acc[2][2],
                          float (*Hs)[66], float (*Ws)[36]) {
    const int tx = tid & 7;
    const int r0 = (tid >> 3) * 2;
    for (int k0 = 0; k0 < K; k0 += 16) {
        {   // h_prev tile: 64 rows x 16 k (transposed)
            int b = tid >> 2, kq = tid & 3;
            float4 v = *(const float4*)(hprev + (size_t)b * hstride + k0 + kq * 4);
            Hs[kq * 4 + 0][b] = v.x; Hs[kq * 4 + 1][b] = v.y;
            Hs[kq * 4 + 2][b] = v.z; Hs[kq * 4 + 3][b] = v.w;
        }
        if (tid < 128) { // W tile: 32 gate-rows x 16 k, layout Ws[k][j*4+g]
            int gj = tid >> 2, kq = tid & 3;
            int j = gj >> 2, g = gj & 3;
            float4 v = *(const float4*)(Whh + (size_t)(g * HHg + j0 + j) * K + k0 + kq * 4);
            Ws[kq * 4 + 0][gj] = v.x; Ws[kq * 4 + 1][gj] = v.y;
            Ws[kq * 4 + 2][gj] = v.z; Ws[kq * 4 + 3][gj] = v.w;
        }
        __syncthreads();
#pragma unroll
        for (int kk = 0; kk < 16; kk++) {
            float2 a   = *(const float2*)&Hs[kk][r0];
            float2 w01 = *(const float2*)&Ws[kk][tx * 4];
            float2 w23 = *(const float2*)&Ws[kk][tx * 4 + 2];
            unsigned long long wp0 = pk2(w01.x, w01.y);
            unsigned long long wp1 = pk2(w23.x, w23.y);
            unsigned long long a0 = pk2(a.x, a.x);
            unsigned long long a1 = pk2(a.y, a.y);
            FMA2(acc[0][0], a0, wp0); FMA2(acc[0][1], a0, wp1);
            FMA2(acc[1][0], a1, wp0); FMA2(acc[1][1], a1, wp1);
        }
        __syncthreads();
    }
}

// ---------------- layer-0 step (both directions via blockIdx.y) -------------
__global__ void k_l0_step(int t,
                          const float* __restrict__ h0f, const float* __restrict__ h0b,
                          const float* __restrict__ whh_f, const float* __restrict__ whh_b) {
    __shared__ float Hs[16][66];
    __shared__ float Ws[16][36];
    const int dir = blockIdx.y;
    const int tid = threadIdx.x;
    const int j0 = blockIdx.x * 8;

    const float* Whh = dir ? whh_b : whh_f;
    const float* pre = (dir ? g_GB : g_GF) + (size_t)((dir ? (S - 1 - t) : t) * Bz) * G4;
    float* Cst = dir ? g_Cb : g_Cf;
    const float* hprev; int hstride;
    if (t == 0) { hprev = dir ? h0b : h0f; hstride = H; }
    else        { hprev = g_XIN + (size_t)(t - 1) * Bz * H2 + dir * H; hstride = H2; }
    float* outp = g_XIN + (size_t)t * Bz * H2 + dir * H;

    unsigned long long acc[2][2] = {{0ull, 0ull}, {0ull, 0ull}};
    step_gemm<H>(hprev, hstride, Whh, H, j0, tid, acc, Hs, Ws);

    const int tx = tid & 7, r0 = (tid >> 3) * 2;
    const int jg = j0 + tx;
#pragma unroll
    for (int r = 0; r < 2; r++) {
        int b = r0 + r;
        float2 if_ = upk2(acc[r][0]);
        float2 go_ = upk2(acc[r][1]);
        const float* pb = pre + (size_t)b * G4;
        float gi = if_.x + pb[0 * H + jg];
        float gf = if_.y + pb[1 * H + jg];
        float gg = go_.x + pb[2 * H + jg];
        float go = go_.y + pb[3 * H + jg];
        float c  = Cst[b * H + jg];
        float c2 = sigf(gf) * c + sigf(gi) * tanhf(gg);
        float h  = sigf(go) * tanhf(c2);
        Cst[b * H + jg] = c2;
        outp[(size_t)b * H2 + jg] = h;
    }
}

// ---------------- layer-1 step A: lstm1 (cell = c2, own c discarded) --------
__global__ void k_l1a_step(int t, const float* __restrict__ whh1) {
    __shared__ float Hs[16][66];
    __shared__ float Ws[16][36];
    const int tid = threadIdx.x;
    const int j0 = blockIdx.x * 8;

    const float* h1prev = (t & 1) ? g_H1b : g_H1a;
    float*       h1out  = (t & 1) ? g_H1a : g_H1b;
    const float* pre = g_G1 + (size_t)t * Bz * G8;

    unsigned long long acc[2][2] = {{0ull, 0ull}, {0ull, 0ull}};
    step_gemm<H2>(h1prev, H2, whh1, H2, j0, tid, acc, Hs, Ws);

    const int tx = tid & 7, r0 = (tid >> 3) * 2;
    const int jg = j0 + tx;
#pragma unroll
    for (int r = 0; r < 2; r++) {
        int b = r0 + r;
        float2 if_ = upk2(acc[r][0]);
        float2 go_ = upk2(acc[r][1]);
        const float* pb = pre + (size_t)b * G8;
        float gi = if_.x + pb[0 * H2 + jg];
        float gf = if_.y + pb[1 * H2 + jg];
        float gg = go_.x + pb[2 * H2 + jg];
        float go = go_.y + pb[3 * H2 + jg];
        float c2 = g_C2[b * H2 + jg];                       // read-only here
        float cc = sigf(gf) * c2 + sigf(gi) * tanhf(gg);    // discarded cell
        h1out[(size_t)b * H2 + jg] = sigf(go) * tanhf(cc);
    }
}

// ---------------- layer-1 step B: lstm2 (two GEMM operands) ------------------
__global__ void k_l1b_step(int t,
                           const float* __restrict__ wih2, const float* __restrict__ whh2,
                           const float* __restrict__ bih2, const float* __restrict__ bhh2) {
    __shared__ float Hs[16][66];
    __shared__ float Ws[16][36];
    const int tid = threadIdx.x;
    const int j0 = blockIdx.x * 8;

    const float* h1n    = (t & 1) ? g_H1a : g_H1b;  // just written by l1a(t)
    const float* h2prev = (t & 1) ? g_H2b : g_H2a;
    float*       h2out  = (t & 1) ? g_H2a : g_H2b;

    unsigned long long acc[2][2] = {{0ull, 0ull}, {0ull, 0ull}};
    step_gemm<H2>(h1n,    H2, wih2, H2, j0, tid, acc, Hs, Ws);
    step_gemm<H2>(h2prev, H2, whh2, H2, j0, tid, acc, Hs, Ws);

    const int tx = tid & 7, r0 = (tid >> 3) * 2;
    const int jg = j0 + tx;
#pragma unroll
    for (int r = 0; r < 2; r++) {
        int b = r0 + r;
        float2 if_ = upk2(acc[r][0]);
        float2 go_ = upk2(acc[r][1]);
        float gi = if_.x + bih2[0 * H2 + jg] + bhh2[0 * H2 + jg];
        float gf = if_.y + bih2[1 * H2 + jg] + bhh2[1 * H2 + jg];
        float gg = go_.x + bih2[2 * H2 + jg] + bhh2[2 * H2 + jg];
        float go = go_.y + bih2[3 * H2 + jg] + bhh2[3 * H2 + jg];
        float c2  = g_C2[b * H2 + jg];
        float c2n = sigf(gf) * c2 + sigf(gi) * tanhf(gg);
        g_C2[b * H2 + jg] = c2n;
        h2out[(size_t)b * H2 + jg] = sigf(go) * tanhf(c2n);
    }
}

// ---------------- launch -----------------------------------------------------
extern "C" void kernel_launch(void* const* d_in, const int* in_sizes, int n_in,
                              void* d_out, int out_size) {
    const int*   x     = (const int*)  d_in[0];
    const float* emb   = (const float*)d_in[1];
    const float* h0f   = (const float*)d_in[2];
    const float* c0f   = (const float*)d_in[3];
    const float* h0b   = (const float*)d_in[4];
    const float* c0b   = (const float*)d_in[5];
    const float* h01   = (const float*)d_in[6];
    const float* h02   = (const float*)d_in[7];
    const float* c02   = (const float*)d_in[8];
    const float* wih_f = (const float*)d_in[9];
    const float* whh_f = (const float*)d_in[10];
    const float* bih_f = (const float*)d_in[11];
    const float* bhh_f = (const float*)d_in[12];
    const float* wih_b = (const float*)d_in[13];
    const float* whh_b = (const float*)d_in[14];
    const float* bih_b = (const float*)d_in[15];
    const float* bhh_b = (const float*)d_in[16];
    const float* wih1  = (const float*)d_in[17];
    const float* whh1  = (const float*)d_in[18];
    const float* bih1  = (const float*)d_in[19];
    const float* bhh1  = (const float*)d_in[20];
    const float* wih2  = (const float*)d_in[21];
    const float* whh2  = (const float*)d_in[22];
    const float* bih2  = (const float*)d_in[23];
    const float* bhh2  = (const float*)d_in[24];
    const float* wlin  = (const float*)d_in[25];
    const float* blin  = (const float*)d_in[26];
    float* out = (float*)d_out;

    float *pX, *pGF, *pGB, *pXIN, *pG1, *pH2a;
    cudaGetSymbolAddress((void**)&pX,   g_X);
    cudaGetSymbolAddress((void**)&pGF,  g_GF);
    cudaGetSymbolAddress((void**)&pGB,  g_GB);
    cudaGetSymbolAddress((void**)&pXIN, g_XIN);
    cudaGetSymbolAddress((void**)&pG1,  g_G1);
    cudaGetSymbolAddress((void**)&pH2a, g_H2a);

    // Phase A: embedding gather + state init
    k_embed<<<R, 128>>>(x, emb);
    k_init<<<1024, 256>>>(h01, h02, c02, c0f, c0b);

    // Phase B: hoisted input-side GEMMs for layer 0
    k_gemm_bias<128><<<dim3(G4 / 64, R / 128), 256>>>(pX, wih_f, bih_f, bhh_f, pGF, H, G4);
    k_gemm_bias<128><<<dim3(G4 / 64, R / 128), 256>>>(pX, wih_b, bih_b, bhh_b, pGB, H, G4);

    // Phase C: layer-0 recurrence (fwd+bwd fused per launch)
    for (int t = 0; t < S; t++)
        k_l0_step<<<dim3(H / 8, 2), 256>>>(t, h0f, h0b, whh_f, whh_b);

    // Phase D: hoisted input-side GEMM for lstm1
    k_gemm_bias<128><<<dim3(G8 / 64, R / 128), 256>>>(pXIN, wih1, bih1, bhh1, pG1, H2, G8);

    // Phase E: layer-1 recurrence (lstm1 then lstm2 per step)
    for (int t = 0; t < S; t++) {
        k_l1a_step<<<H2 / 8, 256>>>(t, whh1);
        k_l1b_step<<<H2 / 8, 256>>>(t, wih2, whh2, bih2, bhh2);
    }

    // Phase F: logits (final h2 lives in g_H2a after t=127)
    k_gemm_bias<64><<<dim3(V / 64, 1), 256>>>(pH2a, wlin, blin, nullptr, out, H2, V);
}

// round 4
// speedup vs baseline: 1.0017x; 1.0017x over previous
#include <cuda_runtime.h>

#define DEV_INLINE __device__ __forceinline__

static constexpr int V  = 32000;
static constexpr int H  = 512;
static constexpr int Bz = 64;
static constexpr int S  = 128;
static constexpr int H2 = 1024;   // 2H
static constexpr int G4 = 2048;   // 4H
static constexpr int G8 = 4096;   // 8H
static constexpr int R  = S * Bz; // 8192 rows of the (S,B) layout

// ---------------- scratch (device globals; no allocation allowed) ----------
__device__ float g_X  [R * H];    // gathered embeddings, (S*B, H)
__device__ float g_GF [R * G4];   // X@wih_f^T + bih_f + bhh_f
__device__ float g_GB [R * G4];   // X@wih_b^T + bih_b + bhh_b
__device__ float g_XIN[R * H2];   // [fwd | bwd] per scan index t
__device__ float g_G1 [R * G8];   // XIN@wih1^T + bih1 + bhh1
__device__ float g_Cf [Bz * H];
__device__ float g_Cb [Bz * H];
__device__ float g_H1a[Bz * H2];
__device__ float g_H1b[Bz * H2];
__device__ float g_H2a[Bz * H2];
__device__ float g_H2b[Bz * H2];
__device__ float g_C2 [Bz * H2];

// ---------------- packed f32x2 helpers -------------------------------------
DEV_INLINE unsigned long long pk2(float x, float y) {
    unsigned long long r;
    asm("mov.b64 %0, {%1, %2};" : "=l"(r) : "f"(x), "f"(y));
    return r;
}
DEV_INLINE float2 upk2(unsigned long long v) {
    float2 r;
    asm("mov.b64 {%0, %1}, %2;" : "=f"(r.x), "=f"(r.y) : "l"(v));
    return r;
}
#define FMA2(d, a, b) asm("fma.rn.f32x2 %0, %1, %2, %0;" : "+l"(d) : "l"(a), "l"(b))

DEV_INLINE float sigf(float x) { return 1.f / (1.f + expf(-x)); }

// ---------------- embedding gather ------------------------------------------
// row r of (S,B,H) = E[x_flat[r]]; token 0 -> zero row (padding_idx)
__global__ void k_embed(const int* __restrict__ x, const float* __restrict__ emb) {
    int r = blockIdx.x;
    int tok = x[r];
    float4 v = make_float4(0.f, 0.f, 0.f, 0.f);
    if (tok != 0)
        v = *(const float4*)(emb + (size_t)tok * H + threadIdx.x * 4);
    *(float4*)(g_X + (size_t)r * H + threadIdx.x * 4) = v;
}

// ---------------- initial-state copy ----------------------------------------
__global__ void k_init(const float* __restrict__ h01, const float* __restrict__ h02,
                       const float* __restrict__ c02, const float* __restrict__ c0f,
                       const float* __restrict__ c0b) {
    int i = blockIdx.x * blockDim.x + threadIdx.x; // 1024*256 = 262144 exactly
    if      (i < 65536)  g_H1a[i]          = h01[i];
    else if (i < 131072) g_H2a[i - 65536]  = h02[i - 65536];
    else if (i < 196608) g_C2 [i - 131072] = c02[i - 131072];
    else if (i < 229376) g_Cf [i - 196608] = c0f[i - 196608];
    else                 g_Cb [i - 229376] = c0b[i - 229376];
}

// ---------------- big batched GEMM: C[M,N] = A[M,K] @ W[N,K]^T + b1 + b2 ----
// 256 threads; BM x 64 tile; per-thread RPT x 4 outputs; f32x2 inner loop.
template <int BM>
__global__ void k_gemm_bias(const float* __restrict__ A,
                            const float* __restrict__ Wt,
                            const float* __restrict__ b1,
                            const float* __restrict__ b2,
                            float* __restrict__ C,
                            int K, int N) {
    constexpr int BN = 64, BK = 16, RPT = BM / 16;
    __shared__ float As[BK][BM + 4];
    __shared__ float Bs[BK][BN + 4];
    const int tid = threadIdx.x;
    const int bm = blockIdx.y * BM, bn = blockIdx.x * BN;
    const int tx = tid & 15, ty = tid >> 4;

    unsigned long long acc[RPT][2];
#pragma unroll
    for (int r = 0; r < RPT; r++) { acc[r][0] = 0ull; acc[r][1] = 0ull; }

    for (int k0 = 0; k0 < K; k0 += BK) {
#pragma unroll
        for (int i = tid; i < BM * 4; i += 256) {
            int m = i >> 2, kq = i & 3;
            float4 v = *(const float4*)(A + (size_t)(bm + m) * K + k0 + kq * 4);
            As[kq * 4 + 0][m] = v.x; As[kq * 4 + 1][m] = v.y;
            As[kq * 4 + 2][m] = v.z; As[kq * 4 + 3][m] = v.w;
        }
        {
            int n = tid >> 2, kq = tid & 3;
            float4 v = *(const float4*)(Wt + (size_t)(bn + n) * K + k0 + kq * 4);
            Bs[kq * 4 + 0][n] = v.x; Bs[kq * 4 + 1][n] = v.y;
            Bs[kq * 4 + 2][n] = v.z; Bs[kq * 4 + 3][n] = v.w;
        }
        __syncthreads();
#pragma unroll
        for (int kk = 0; kk < BK; kk++) {
            float2 bv0 = *(const float2*)&Bs[kk][tx * 4];
            float2 bv1 = *(const float2*)&Bs[kk][tx * 4 + 2];
            unsigned long long bp0 = pk2(bv0.x, bv0.y);
            unsigned long long bp1 = pk2(bv1.x, bv1.y);
#pragma unroll
            for (int r = 0; r < RPT; r++) {
                float a = As[kk][ty * RPT + r];
                unsigned long long ap = pk2(a, a);
                FMA2(acc[r][0], ap, bp0);
                FMA2(acc[r][1], ap, bp1);
            }
        }
        __syncthreads();
    }

    const int ncol = bn + tx * 4;
    float bb0 = b1[ncol + 0] + (b2 ? b2[ncol + 0] : 0.f);
    float bb1 = b1[ncol + 1] + (b2 ? b2[ncol + 1] : 0.f);
    float bb2 = b1[ncol + 2] + (b2 ? b2[ncol + 2] : 0.f);
    float bb3 = b1[ncol + 3] + (b2 ? b2[ncol + 3] : 0.f);
#pragma unroll
    for (int r = 0; r < RPT; r++) {
        float2 v0 = upk2(acc[r][0]);
        float2 v1 = upk2(acc[r][1]);
        float4 o = make_float4(v0.x + bb0, v0.y + bb1, v1.x + bb2, v1.y + bb3);
        *(float4*)(C + (size_t)(bm + ty * RPT + r) * N + ncol) = o;
    }
}

// ---------------- fused step GEMM core --------------------------------------
// Block covers 64 batch rows x (8 j-cols x 4 gates). acc[r][0]=(i,f), acc[r][1]=(g,o)
// for rows r0, r0+1.  HHg = gate stride in W's row index (H or H2).
template <int HHg>
DEV_INLINE void step_gemm(const float* __restrict__ hprev, int hstride,
                          const float* __restrict__ Whh, int K,
                          int j0, int tid,
                          unsigned long long acc[2][2],
                          float (*Hs)[66], float (*Ws)[36]) {
    const int tx = tid & 7;
    const int r0 = (tid >> 3) * 2;
    for (int k0 = 0; k0 < K; k0 += 16) {
        {   // h_prev tile: 64 rows x 16 k (transposed)
            int b = tid >> 2, kq = tid & 3;
            float4 v = *(const float4*)(hprev + (size_t)b * hstride + k0 + kq * 4);
            Hs[kq * 4 + 0][b] = v.x; Hs[kq * 4 + 1][b] = v.y;
            Hs[kq * 4 + 2][b] = v.z; Hs[kq * 4 + 3][b] = v.w;
        }
        if (tid < 128) { // W tile: 32 gate-rows x 16 k, layout Ws[k][j*4+g]
            int gj = tid >> 2, kq = tid & 3;
            int j = gj >> 2, g = gj & 3;
            float4 v = *(const float4*)(Whh + (size_t)(g * HHg + j0 + j) * K + k0 + kq * 4);
            Ws[kq * 4 + 0][gj] = v.x; Ws[kq * 4 + 1][gj] = v.y;
            Ws[kq * 4 + 2][gj] = v.z; Ws[kq * 4 + 3][gj] = v.w;
        }
        __syncthreads();
#pragma unroll
        for (int kk = 0; kk < 16; kk++) {
            float2 a   = *(const float2*)&Hs[kk][r0];
            float2 w01 = *(const float2*)&Ws[kk][tx * 4];
            float2 w23 = *(const float2*)&Ws[kk][tx * 4 + 2];
            unsigned long long wp0 = pk2(w01.x, w01.y);
            unsigned long long wp1 = pk2(w23.x, w23.y);
            unsigned long long a0 = pk2(a.x, a.x);
            unsigned long long a1 = pk2(a.y, a.y);
            FMA2(acc[0][0], a0, wp0); FMA2(acc[0][1], a0, wp1);
            FMA2(acc[1][0], a1, wp0); FMA2(acc[1][1], a1, wp1);
        }
        __syncthreads();
    }
}

// ---------------- layer-0 step (both directions via blockIdx.y) -------------
__global__ void k_l0_step(int t,
                          const float* __restrict__ h0f, const float* __restrict__ h0b,
                          const float* __restrict__ whh_f, const float* __restrict__ whh_b) {
    __shared__ float Hs[16][66];
    __shared__ float Ws[16][36];
    const int dir = blockIdx.y;
    const int tid = threadIdx.x;
    const int j0 = blockIdx.x * 8;

    const float* Whh = dir ? whh_b : whh_f;
    const float* pre = (dir ? g_GB : g_GF) + (size_t)((dir ? (S - 1 - t) : t) * Bz) * G4;
    float* Cst = dir ? g_Cb : g_Cf;
    const float* hprev; int hstride;
    if (t == 0) { hprev = dir ? h0b : h0f; hstride = H; }
    else        { hprev = g_XIN + (size_t)(t - 1) * Bz * H2 + dir * H; hstride = H2; }
    float* outp = g_XIN + (size_t)t * Bz * H2 + dir * H;

    unsigned long long acc[2][2] = {{0ull, 0ull}, {0ull, 0ull}};
    step_gemm<H>(hprev, hstride, Whh, H, j0, tid, acc, Hs, Ws);

    const int tx = tid & 7, r0 = (tid >> 3) * 2;
    const int jg = j0 + tx;
#pragma unroll
    for (int r = 0; r < 2; r++) {
        int b = r0 + r;
        float2 if_ = upk2(acc[r][0]);
        float2 go_ = upk2(acc[r][1]);
        const float* pb = pre + (size_t)b * G4;
        float gi = if_.x + pb[0 * H + jg];
        float gf = if_.y + pb[1 * H + jg];
        float gg = go_.x + pb[2 * H + jg];
        float go = go_.y + pb[3 * H + jg];
        float c  = Cst[b * H + jg];
        float c2 = sigf(gf) * c + sigf(gi) * tanhf(gg);
        float h  = sigf(go) * tanhf(c2);
        Cst[b * H + jg] = c2;
        outp[(size_t)b * H2 + jg] = h;
    }
}

// ---------------- layer-1 step A: lstm1 (cell = c2, own c discarded) --------
__global__ void k_l1a_step(int t, const float* __restrict__ whh1) {
    __shared__ float Hs[16][66];
    __shared__ float Ws[16][36];
    const int tid = threadIdx.x;
    const int j0 = blockIdx.x * 8;

    const float* h1prev = (t & 1) ? g_H1b : g_H1a;
    float*       h1out  = (t & 1) ? g_H1a : g_H1b;
    const float* pre = g_G1 + (size_t)t * Bz * G8;

    unsigned long long acc[2][2] = {{0ull, 0ull}, {0ull, 0ull}};
    step_gemm<H2>(h1prev, H2, whh1, H2, j0, tid, acc, Hs, Ws);

    const int tx = tid & 7, r0 = (tid >> 3) * 2;
    const int jg = j0 + tx;
#pragma unroll
    for (int r = 0; r < 2; r++) {
        int b = r0 + r;
        float2 if_ = upk2(acc[r][0]);
        float2 go_ = upk2(acc[r][1]);
        const float* pb = pre + (size_t)b * G8;
        float gi = if_.x + pb[0 * H2 + jg];
        float gf = if_.y + pb[1 * H2 + jg];
        float gg = go_.x + pb[2 * H2 + jg];
        float go = go_.y + pb[3 * H2 + jg];
        float c2 = g_C2[b * H2 + jg];                       // read-only here
        float cc = sigf(gf) * c2 + sigf(gi) * tanhf(gg);    // discarded cell
        h1out[(size_t)b * H2 + jg] = sigf(go) * tanhf(cc);
    }
}

// ---------------- layer-1 step B: lstm2 (two GEMM operands) ------------------
__global__ void k_l1b_step(int t,
                           const float* __restrict__ wih2, const float* __restrict__ whh2,
                           const float* __restrict__ bih2, const float* __restrict__ bhh2) {
    __shared__ float Hs[16][66];
    __shared__ float Ws[16][36];
    const int tid = threadIdx.x;
    const int j0 = blockIdx.x * 8;

    const float* h1n    = (t & 1) ? g_H1a : g_H1b;  // just written by l1a(t)
    const float* h2prev = (t & 1) ? g_H2b : g_H2a;
    float*       h2out  = (t & 1) ? g_H2a : g_H2b;

    unsigned long long acc[2][2] = {{0ull, 0ull}, {0ull, 0ull}};
    step_gemm<H2>(h1n,    H2, wih2, H2, j0, tid, acc, Hs, Ws);
    step_gemm<H2>(h2prev, H2, whh2, H2, j0, tid, acc, Hs, Ws);

    const int tx = tid & 7, r0 = (tid >> 3) * 2;
    const int jg = j0 + tx;
#pragma unroll
    for (int r = 0; r < 2; r++) {
        int b = r0 + r;
        float2 if_ = upk2(acc[r][0]);
        float2 go_ = upk2(acc[r][1]);
        float gi = if_.x + bih2[0 * H2 + jg] + bhh2[0 * H2 + jg];
        float gf = if_.y + bih2[1 * H2 + jg] + bhh2[1 * H2 + jg];
        float gg = go_.x + bih2[2 * H2 + jg] + bhh2[2 * H2 + jg];
        float go = go_.y + bih2[3 * H2 + jg] + bhh2[3 * H2 + jg];
        float c2  = g_C2[b * H2 + jg];
        float c2n = sigf(gf) * c2 + sigf(gi) * tanhf(gg);
        g_C2[b * H2 + jg] = c2n;
        h2out[(size_t)b * H2 + jg] = sigf(go) * tanhf(c2n);
    }
}

// ---------------- launch -----------------------------------------------------
extern "C" void kernel_launch(void* const* d_in, const int* in_sizes, int n_in,
                              void* d_out, int out_size) {
    const int*   x     = (const int*)  d_in[0];
    const float* emb   = (const float*)d_in[1];
    const float* h0f   = (const float*)d_in[2];
    const float* c0f   = (const float*)d_in[3];
    const float* h0b   = (const float*)d_in[4];
    const float* c0b   = (const float*)d_in[5];
    const float* h01   = (const float*)d_in[6];
    const float* h02   = (const float*)d_in[7];
    const float* c02   = (const float*)d_in[8];
    const float* wih_f = (const float*)d_in[9];
    const float* whh_f = (const float*)d_in[10];
    const float* bih_f = (const float*)d_in[11];
    const float* bhh_f = (const float*)d_in[12];
    const float* wih_b = (const float*)d_in[13];
    const float* whh_b = (const float*)d_in[14];
    const float* bih_b = (const float*)d_in[15];
    const float* bhh_b = (const float*)d_in[16];
    const float* wih1  = (const float*)d_in[17];
    const float* whh1  = (const float*)d_in[18];
    const float* bih1  = (const float*)d_in[19];
    const float* bhh1  = (const float*)d_in[20];
    const float* wih2  = (const float*)d_in[21];
    const float* whh2  = (const float*)d_in[22];
    const float* bih2  = (const float*)d_in[23];
    const float* bhh2  = (const float*)d_in[24];
    const float* wlin  = (const float*)d_in[25];
    const float* blin  = (const float*)d_in[26];
    float* out = (float*)d_out;

    float *pX, *pGF, *pGB, *pXIN, *pG1, *pH2a;
    cudaGetSymbolAddress((void**)&pX,   g_X);
    cudaGetSymbolAddress((void**)&pGF,  g_GF);
    cudaGetSymbolAddress((void**)&pGB,  g_GB);
    cudaGetSymbolAddress((void**)&pXIN, g_XIN);
    cudaGetSymbolAddress((void**)&pG1,  g_G1);
    cudaGetSymbolAddress((void**)&pH2a, g_H2a);

    // Phase A: embedding gather + state init
    k_embed<<<R, 128>>>(x, emb);
    k_init<<<1024, 256>>>(h01, h02, c02, c0f, c0b);

    // Phase B: hoisted input-side GEMMs for layer 0
    k_gemm_bias<128><<<dim3(G4 / 64, R / 128), 256>>>(pX, wih_f, bih_f, bhh_f, pGF, H, G4);
    k_gemm_bias<128><<<dim3(G4 / 64, R / 128), 256>>>(pX, wih_b, bih_b, bhh_b, pGB, H, G4);

    // Phase C: layer-0 recurrence (fwd+bwd fused per launch)
    for (int t = 0; t < S; t++)
        k_l0_step<<<dim3(H / 8, 2), 256>>>(t, h0f, h0b, whh_f, whh_b);

    // Phase D: hoisted input-side GEMM for lstm1
    k_gemm_bias<128><<<dim3(G8 / 64, R / 128), 256>>>(pXIN, wih1, bih1, bhh1, pG1, H2, G8);

    // Phase E: layer-1 recurrence (lstm1 then lstm2 per step)
    for (int t = 0; t < S; t++) {
        k_l1a_step<<<H2 / 8, 256>>>(t, whh1);
        k_l1b_step<<<H2 / 8, 256>>>(t, wih2, whh2, bih2, bhh2);
    }

    // Phase F: logits (final h2 lives in g_H2a after t=127)
    k_gemm_bias<64><<<dim3(V / 64, 1), 256>>>(pH2a, wlin, blin, nullptr, out, H2, V);
}

// round 5
// speedup vs baseline: 1.2783x; 1.2761x over previous
#include <cuda_runtime.h>

#define DEV_INLINE __device__ __forceinline__
typedef unsigned long long u64;

static constexpr int V  = 32000;
static constexpr int H  = 512;
static constexpr int Bz = 64;
static constexpr int S  = 128;
static constexpr int H2 = 1024;
static constexpr int G4 = 2048;
static constexpr int G8 = 4096;
static constexpr int R  = S * Bz;

// ---------------- scratch ---------------------------------------------------
__device__ float g_X   [R * H];
__device__ float g_GF  [R * G4];
__device__ float g_GB  [R * G4];
__device__ float g_XIN [R * H2];          // row-major, operand of phase D
__device__ float g_XINT[R * H2];          // per t transposed: [t][k][b]
__device__ float g_G1  [R * G8];
__device__ float g_H0T [2 * H * Bz];      // transposed h0f|h0b
__device__ float g_H1T [2 * H2 * Bz];     // ping-pong transposed
__device__ float g_H2T [2 * H2 * Bz];
__device__ float g_H2R [Bz * H2];         // final h2 row-major
__device__ unsigned g_bar0, g_bar1;

// ---------------- helpers ---------------------------------------------------
DEV_INLINE u64 pk2(float x, float y) {
    u64 r; asm("mov.b64 %0, {%1, %2};" : "=l"(r) : "f"(x), "f"(y)); return r;
}
DEV_INLINE float2 upk2(u64 v) {
    float2 r; asm("mov.b64 {%0, %1}, %2;" : "=f"(r.x), "=f"(r.y) : "l"(v)); return r;
}
#define FMA2(d, a, b) asm("fma.rn.f32x2 %0, %1, %2, %0;" : "+l"(d) : "l"(a), "l"(b))
DEV_INLINE float sigf(float x) { return 1.f / (1.f + expf(-x)); }
DEV_INLINE float4 ldcg4(const float* p) { return __ldcg((const float4*)p); }

DEV_INLINE void gbar(unsigned* cnt, unsigned target) {
    __threadfence();
    __syncthreads();
    if (threadIdx.x == 0) {
        atomicAdd(cnt, 1u);
        while (atomicAdd(cnt, 0u) < target) __nanosleep(64);
    }
    __syncthreads();
}

// ---------------- embedding gather ------------------------------------------
__global__ void k_embed(const int* __restrict__ x, const float* __restrict__ emb) {
    int r = blockIdx.x;
    int tok = x[r];
    float4 v = make_float4(0.f, 0.f, 0.f, 0.f);
    if (tok != 0) v = *(const float4*)(emb + (size_t)tok * H + threadIdx.x * 4);
    *(float4*)(g_X + (size_t)r * H + threadIdx.x * 4) = v;
}

// ---------------- init: transpose states, zero barriers ----------------------
__global__ void k_init(const float* __restrict__ h01, const float* __restrict__ h02,
                       const float* __restrict__ h0f, const float* __restrict__ h0b) {
    int i = blockIdx.x * blockDim.x + threadIdx.x;   // 768*256 = 196608
    if (i == 0) { g_bar0 = 0u; g_bar1 = 0u; }
    if (i < 65536) {
        int b = i >> 10, k = i & 1023;
        g_H1T[k * Bz + b] = h01[i];
    } else if (i < 131072) {
        int j = i - 65536, b = j >> 10, k = j & 1023;
        g_H2T[k * Bz + b] = h02[j];
    } else {
        int j = i - 131072, d = j >> 15, r = j & 32767;
        int b = r >> 9, k = r & 511;
        g_H0T[d * (H * Bz) + k * Bz + b] = (d ? h0b : h0f)[r];
    }
}

// ---------------- big batched GEMM (unchanged, proven) ------------------------
template <int BM>
__global__ void k_gemm_bias(const float* __restrict__ A, const float* __restrict__ Wt,
                            const float* __restrict__ b1, const float* __restrict__ b2,
                            float* __restrict__ C, int K, int N) {
    constexpr int BN = 64, BK = 16, RPT = BM / 16;
    __shared__ float As[BK][BM + 4];
    __shared__ float Bs[BK][BN + 4];
    const int tid = threadIdx.x;
    const int bm = blockIdx.y * BM, bn = blockIdx.x * BN;
    const int tx = tid & 15, ty = tid >> 4;
    u64 acc[RPT][2];
#pragma unroll
    for (int r = 0; r < RPT; r++) { acc[r][0] = 0ull; acc[r][1] = 0ull; }
    for (int k0 = 0; k0 < K; k0 += BK) {
#pragma unroll
        for (int i = tid; i < BM * 4; i += 256) {
            int m = i >> 2, kq = i & 3;
            float4 v = *(const float4*)(A + (size_t)(bm + m) * K + k0 + kq * 4);
            As[kq * 4 + 0][m] = v.x; As[kq * 4 + 1][m] = v.y;
            As[kq * 4 + 2][m] = v.z; As[kq * 4 + 3][m] = v.w;
        }
        {
            int n = tid >> 2, kq = tid & 3;
            float4 v = *(const float4*)(Wt + (size_t)(bn + n) * K + k0 + kq * 4);
            Bs[kq * 4 + 0][n] = v.x; Bs[kq * 4 + 1][n] = v.y;
            Bs[kq * 4 + 2][n] = v.z; Bs[kq * 4 + 3][n] = v.w;
        }
        __syncthreads();
#pragma unroll
        for (int kk = 0; kk < BK; kk++) {
            float2 bv0 = *(const float2*)&Bs[kk][tx * 4];
            float2 bv1 = *(const float2*)&Bs[kk][tx * 4 + 2];
            u64 bp0 = pk2(bv0.x, bv0.y), bp1 = pk2(bv1.x, bv1.y);
#pragma unroll
            for (int r = 0; r < RPT; r++) {
                float a = As[kk][ty * RPT + r];
                u64 ap = pk2(a, a);
                FMA2(acc[r][0], ap, bp0);
                FMA2(acc[r][1], ap, bp1);
            }
        }
        __syncthreads();
    }
    const int ncol = bn + tx * 4;
    float bb0 = b1[ncol + 0] + (b2 ? b2[ncol + 0] : 0.f);
    float bb1 = b1[ncol + 1] + (b2 ? b2[ncol + 1] : 0.f);
    float bb2 = b1[ncol + 2] + (b2 ? b2[ncol + 2] : 0.f);
    float bb3 = b1[ncol + 3] + (b2 ? b2[ncol + 3] : 0.f);
#pragma unroll
    for (int r = 0; r < RPT; r++) {
        float2 v0 = upk2(acc[r][0]);
        float2 v1 = upk2(acc[r][1]);
        float4 o = make_float4(v0.x + bb0, v0.y + bb1, v1.x + bb2, v1.y + bb3);
        *(float4*)(C + (size_t)(bm + ty * RPT + r) * N + ncol) = o;
    }
}

// ---------------- persistent layer-0 ----------------------------------------
// 128 blocks = 64 j-slices x 2 dirs; W slice resident in SMEM; c in registers.
__global__ void __launch_bounds__(256, 1) k_l0_persist(
        const float* __restrict__ c0f, const float* __restrict__ c0b,
        const float* __restrict__ whh_f, const float* __restrict__ whh_b) {
    extern __shared__ float sm[];
    float* Ws = sm;                 // [512][32]
    float* Hs = sm + 512 * 32;      // [2][64][68]
    const int tid = threadIdx.x;
    const int dir = blockIdx.x >> 6;
    const int j0  = (blockIdx.x & 63) * 8;
    const int tx = tid & 7, r0 = (tid >> 3) * 2;
    const int jg = j0 + tx;
    const float* Whh  = dir ? whh_b : whh_f;
    const float* preB = dir ? g_GB  : g_GF;
    const float* c0   = dir ? c0b   : c0f;

    {   // cache W slice once: Ws[k][gj], gj = j*4 + gate
        const int gj = tid & 31, kq = tid >> 5;
        const float* wr = Whh + (size_t)((gj & 3) * H + j0 + (gj >> 2)) * H + kq * 64;
#pragma unroll
        for (int i = 0; i < 16; i++) {
            float4 v = __ldg((const float4*)(wr + i * 4));
            int k = kq * 64 + i * 4;
            Ws[(k + 0) * 32 + gj] = v.x; Ws[(k + 1) * 32 + gj] = v.y;
            Ws[(k + 2) * 32 + gj] = v.z; Ws[(k + 3) * 32 + gj] = v.w;
        }
    }
    float cst[2] = { c0[(r0 + 0) * H + jg], c0[(r0 + 1) * H + jg] };
    __syncthreads();

    for (int t = 0; t < S; t++) {
        const float* hT = (t == 0) ? (g_H0T + dir * (H * Bz))
                                   : (g_XINT + ((size_t)(t - 1) * H2 + dir * H) * Bz);
        u64 acc[2][2] = {{0ull, 0ull}, {0ull, 0ull}};
        float4 hv[4];
#pragma unroll
        for (int i = 0; i < 4; i++) hv[i] = ldcg4(hT + (i * 256 + tid) * 4);
#pragma unroll
        for (int i = 0; i < 4; i++) {
            int f4 = i * 256 + tid;
            *(float4*)&Hs[(f4 >> 4) * 68 + (f4 & 15) * 4] = hv[i];
        }
        __syncthreads();
        for (int kt = 0; kt < 8; kt++) {
            int cur = kt & 1;
            if (kt < 7) {
#pragma unroll
                for (int i = 0; i < 4; i++)
                    hv[i] = ldcg4(hT + ((kt + 1) * 1024 + i * 256 + tid) * 4);
            }
            const float* Hc = Hs + cur * (64 * 68);
            const float* Wk = Ws + kt * 64 * 32;
#pragma unroll 8
            for (int kk = 0; kk < 64; kk++) {
                float2 a = *(const float2*)&Hc[kk * 68 + r0];
                u64 wif = *(const u64*)&Wk[kk * 32 + tx * 4];
                u64 wgo = *(const u64*)&Wk[kk * 32 + tx * 4 + 2];
                u64 a0 = pk2(a.x, a.x), a1 = pk2(a.y, a.y);
                FMA2(acc[0][0], a0, wif); FMA2(acc[0][1], a0, wgo);
                FMA2(acc[1][0], a1, wif); FMA2(acc[1][1], a1, wgo);
            }
            if (kt < 7) {
                float* Hn = Hs + (cur ^ 1) * (64 * 68);
#pragma unroll
                for (int i = 0; i < 4; i++) {
                    int f4 = i * 256 + tid;
                    *(float4*)&Hn[(f4 >> 4) * 68 + (f4 & 15) * 4] = hv[i];
                }
            }
            __syncthreads();
        }
        // fused gate epilogue
        const float* pre = preB + (size_t)(dir ? (S - 1 - t) : t) * Bz * G4;
#pragma unroll
        for (int r = 0; r < 2; r++) {
            int b = r0 + r;
            float2 if_ = upk2(acc[r][0]);
            float2 go_ = upk2(acc[r][1]);
            const float* pb = pre + (size_t)b * G4;
            float gi = if_.x + pb[0 * H + jg];
            float gf = if_.y + pb[1 * H + jg];
            float gg = go_.x + pb[2 * H + jg];
            float go = go_.y + pb[3 * H + jg];
            float c2 = sigf(gf) * cst[r] + sigf(gi) * tanhf(gg);
            cst[r] = c2;
            float h = sigf(go) * tanhf(c2);
            g_XIN [((size_t)t * Bz + b) * H2 + dir * H + jg] = h;
            g_XINT[((size_t)t * H2 + dir * H + jg) * Bz + b] = h;
        }
        gbar(&g_bar0, 128u * (t + 1));
    }
}

// ---------------- layer-1 streaming tile GEMM (K=1024) ------------------------
DEV_INLINE void l1_gemm(const float* __restrict__ hT, const float* __restrict__ W,
                        int j0, int tid, u64 acc[2][2], float* Hs, float* Ws) {
    const int tx = tid & 7, r0 = (tid >> 3) * 2;
    const int gj = tid & 31, kq = tid >> 5;
    const float* wrow = W + (size_t)((gj & 3) * H2 + j0 + (gj >> 2)) * H2 + kq * 8;
    float4 hv[4], wv[2];
#pragma unroll
    for (int i = 0; i < 4; i++) hv[i] = ldcg4(hT + (i * 256 + tid) * 4);
#pragma unroll
    for (int i = 0; i < 2; i++) wv[i] = __ldg((const float4*)(wrow + i * 4));
#pragma unroll
    for (int i = 0; i < 4; i++) {
        int f4 = i * 256 + tid;
        *(float4*)&Hs[(f4 >> 4) * 68 + (f4 & 15) * 4] = hv[i];
    }
#pragma unroll
    for (int i = 0; i < 2; i++) {
        int k = kq * 8 + i * 4;
        Ws[(k + 0) * 32 + gj] = wv[i].x; Ws[(k + 1) * 32 + gj] = wv[i].y;
        Ws[(k + 2) * 32 + gj] = wv[i].z; Ws[(k + 3) * 32 + gj] = wv[i].w;
    }
    __syncthreads();
    for (int kt = 0; kt < 16; kt++) {
        int cur = kt & 1;
        if (kt < 15) {
#pragma unroll
            for (int i = 0; i < 4; i++)
                hv[i] = ldcg4(hT + ((kt + 1) * 1024 + i * 256 + tid) * 4);
#pragma unroll
            for (int i = 0; i < 2; i++)
                wv[i] = __ldg((const float4*)(wrow + (kt + 1) * 64 + i * 4));
        }
        const float* Hc = Hs + cur * (64 * 68);
        const float* Wc = Ws + cur * (64 * 32);
#pragma unroll 8
        for (int kk = 0; kk < 64; kk++) {
            float2 a = *(const float2*)&Hc[kk * 68 + r0];
            u64 wif = *(const u64*)&Wc[kk * 32 + tx * 4];
            u64 wgo = *(const u64*)&Wc[kk * 32 + tx * 4 + 2];
            u64 a0 = pk2(a.x, a.x), a1 = pk2(a.y, a.y);
            FMA2(acc[0][0], a0, wif); FMA2(acc[0][1], a0, wgo);
            FMA2(acc[1][0], a1, wif); FMA2(acc[1][1], a1, wgo);
        }
        if (kt < 15) {
            float* Hn = Hs + (cur ^ 1) * (64 * 68);
            float* Wn = Ws + (cur ^ 1) * (64 * 32);
#pragma unroll
            for (int i = 0; i < 4; i++) {
                int f4 = i * 256 + tid;
                *(float4*)&Hn[(f4 >> 4) * 68 + (f4 & 15) * 4] = hv[i];
            }
#pragma unroll
            for (int i = 0; i < 2; i++) {
                int k = kq * 8 + i * 4;
                Wn[(k + 0) * 32 + gj] = wv[i].x; Wn[(k + 1) * 32 + gj] = wv[i].y;
                Wn[(k + 2) * 32 + gj] = wv[i].z; Wn[(k + 3) * 32 + gj] = wv[i].w;
            }
        }
        __syncthreads();
    }
}

// ---------------- persistent layer-1 -----------------------------------------
__global__ void __launch_bounds__(256, 1) k_l1_persist(
        const float* __restrict__ c02,
        const float* __restrict__ whh1, const float* __restrict__ wih2,
        const float* __restrict__ whh2,
        const float* __restrict__ bih2, const float* __restrict__ bhh2) {
    extern __shared__ float sm[];
    float* Ws = sm;                   // [2][64][32]
    float* Hs = sm + 2 * 64 * 32;     // [2][64][68]
    const int tid = threadIdx.x;
    const int j0 = blockIdx.x * 8;
    const int tx = tid & 7, r0 = (tid >> 3) * 2;
    const int jg = j0 + tx;

    float c2[2] = { c02[(r0 + 0) * H2 + jg], c02[(r0 + 1) * H2 + jg] };
    float bs[4];
#pragma unroll
    for (int g = 0; g < 4; g++) bs[g] = bih2[g * H2 + jg] + bhh2[g * H2 + jg];

    unsigned bt = 0;
    for (int t = 0; t < S; t++) {
        int p = t & 1;
        const float* h1prev = g_H1T + p * (H2 * Bz);
        float*       h1out  = g_H1T + (p ^ 1) * (H2 * Bz);
        const float* h2prev = g_H2T + p * (H2 * Bz);
        float*       h2out  = g_H2T + (p ^ 1) * (H2 * Bz);

        // ---- lstm1: whh1 @ h1prev, cell input = c2 (own cell discarded) ----
        u64 acc[2][2] = {{0ull, 0ull}, {0ull, 0ull}};
        l1_gemm(h1prev, whh1, j0, tid, acc, Hs, Ws);
        const float* pre = g_G1 + (size_t)t * Bz * G8;
#pragma unroll
        for (int r = 0; r < 2; r++) {
            int b = r0 + r;
            float2 if_ = upk2(acc[r][0]);
            float2 go_ = upk2(acc[r][1]);
            const float* pb = pre + (size_t)b * G8;
            float gi = if_.x + pb[0 * H2 + jg];
            float gf = if_.y + pb[1 * H2 + jg];
            float gg = go_.x + pb[2 * H2 + jg];
            float go = go_.y + pb[3 * H2 + jg];
            float cc = sigf(gf) * c2[r] + sigf(gi) * tanhf(gg);
            h1out[(size_t)jg * Bz + b] = sigf(go) * tanhf(cc);
        }
        // ---- lstm2 part A: whh2 @ h2prev (independent of h1out) ----
        acc[0][0] = acc[0][1] = acc[1][0] = acc[1][1] = 0ull;
        l1_gemm(h2prev, whh2, j0, tid, acc, Hs, Ws);
        bt += 128; gbar(&g_bar1, bt);            // h1out now globally visible
        // ---- lstm2 part B: wih2 @ h1new ----
        l1_gemm(h1out, wih2, j0, tid, acc, Hs, Ws);
#pragma unroll
        for (int r = 0; r < 2; r++) {
            int b = r0 + r;
            float2 if_ = upk2(acc[r][0]);
            float2 go_ = upk2(acc[r][1]);
            float gi = if_.x + bs[0];
            float gf = if_.y + bs[1];
            float gg = go_.x + bs[2];
            float go = go_.y + bs[3];
            float cn = sigf(gf) * c2[r] + sigf(gi) * tanhf(gg);
            c2[r] = cn;
            float h2v = sigf(go) * tanhf(cn);
            h2out[(size_t)jg * Bz + b] = h2v;
            if (t == S - 1) g_H2R[(size_t)b * H2 + jg] = h2v;
        }
        bt += 128; gbar(&g_bar1, bt);            // h2out visible for next step
    }
}

// ---------------- launch -----------------------------------------------------
extern "C" void kernel_launch(void* const* d_in, const int* in_sizes, int n_in,
                              void* d_out, int out_size) {
    const int*   x     = (const int*)  d_in[0];
    const float* emb   = (const float*)d_in[1];
    const float* h0f   = (const float*)d_in[2];
    const float* c0f   = (const float*)d_in[3];
    const float* h0b   = (const float*)d_in[4];
    const float* c0b   = (const float*)d_in[5];
    const float* h01   = (const float*)d_in[6];
    const float* h02   = (const float*)d_in[7];
    const float* c02   = (const float*)d_in[8];
    const float* wih_f = (const float*)d_in[9];
    const float* whh_f = (const float*)d_in[10];
    const float* bih_f = (const float*)d_in[11];
    const float* bhh_f = (const float*)d_in[12];
    const float* wih_b = (const float*)d_in[13];
    const float* whh_b = (const float*)d_in[14];
    const float* bih_b = (const float*)d_in[15];
    const float* bhh_b = (const float*)d_in[16];
    const float* wih1  = (const float*)d_in[17];
    const float* whh1  = (const float*)d_in[18];
    const float* bih1  = (const float*)d_in[19];
    const float* bhh1  = (const float*)d_in[20];
    const float* wih2  = (const float*)d_in[21];
    const float* whh2  = (const float*)d_in[22];
    const float* bih2  = (const float*)d_in[23];
    const float* bhh2  = (const float*)d_in[24];
    const float* wlin  = (const float*)d_in[25];
    const float* blin  = (const float*)d_in[26];
    float* out = (float*)d_out;

    float *pX, *pGF, *pGB, *pXIN, *pG1, *pH2R;
    cudaGetSymbolAddress((void**)&pX,   g_X);
    cudaGetSymbolAddress((void**)&pGF,  g_GF);
    cudaGetSymbolAddress((void**)&pGB,  g_GB);
    cudaGetSymbolAddress((void**)&pXIN, g_XIN);
    cudaGetSymbolAddress((void**)&pG1,  g_G1);
    cudaGetSymbolAddress((void**)&pH2R, g_H2R);

    const int L0_SM = (512 * 32 + 2 * 64 * 68) * 4;          // 100352 B
    const int L1_SM = (2 * 64 * 32 + 2 * 64 * 68) * 4;       // 51200 B
    cudaFuncSetAttribute(k_l0_persist, cudaFuncAttributeMaxDynamicSharedMemorySize, L0_SM);
    cudaFuncSetAttribute(k_l1_persist, cudaFuncAttributeMaxDynamicSharedMemorySize, L1_SM);

    // A: gather + init (also zeroes barrier counters each replay)
    k_embed<<<R, 128>>>(x, emb);
    k_init<<<768, 256>>>(h01, h02, h0f, h0b);

    // B: hoisted input-side gate GEMMs for layer 0
    k_gemm_bias<128><<<dim3(G4 / 64, R / 128), 256>>>(pX, wih_f, bih_f, bhh_f, pGF, H, G4);
    k_gemm_bias<128><<<dim3(G4 / 64, R / 128), 256>>>(pX, wih_b, bih_b, bhh_b, pGB, H, G4);

    // C: persistent bidirectional layer-0 recurrence (one launch)
    k_l0_persist<<<128, 256, L0_SM>>>(c0f, c0b, whh_f, whh_b);

    // D: hoisted input-side GEMM for lstm1
    k_gemm_bias<128><<<dim3(G8 / 64, R / 128), 256>>>(pXIN, wih1, bih1, bhh1, pG1, H2, G8);

    // E: persistent layer-1 recurrence (one launch)
    k_l1_persist<<<128, 256, L1_SM>>>(c02, whh1, wih2, whh2, bih2, bhh2);

    // F: logits
    k_gemm_bias<64><<<dim3(V / 64, 1), 256>>>(pH2R, wlin, blin, nullptr, out, H2, V);
}